// round 1
// baseline (speedup 1.0000x reference)
#include <cuda_runtime.h>

#define BATCH 16
#define NNODE 32
#define DEG 64
#define KNN 8
#define IN_F 128
#define OUT_F 3
#define NPTS 2048   // NNODE*DEG
#define JCOLS 8192  // DEG*IN_F

// ---------- device scratch (no allocations allowed) ----------
__device__ float  g_root[BATCH * NNODE * OUT_F];
__device__ float  g_Wl[IN_F * OUT_F];     // collapsed Wl1@Wl2, layout [f*3+o]
__device__ float  g_ceff[OUT_F * 6];      // collapsed c2w@c1w, layout [p*6+c]
__device__ float  g_beff[OUT_F];          // c2w@c1b + c2b
__device__ float4 g_x[BATCH * NPTS];      // (x0,x1,x2, ||x||^2)

// ---------- packed f32x2 helpers ----------
__device__ __forceinline__ unsigned long long splat2(float w) {
    unsigned long long r;
    asm("mov.b64 %0, {%1, %1};" : "=l"(r) : "f"(w));
    return r;
}
__device__ __forceinline__ void ffma2(unsigned long long& d,
                                      unsigned long long a,
                                      unsigned long long b) {
    asm("fma.rn.f32x2 %0, %1, %2, %0;" : "+l"(d) : "l"(a), "l"(b));
}

// ============================================================
// K0: root (B,32,3) + weight collapses. Tiny.
// ============================================================
__global__ void k0_prep(const float* __restrict__ t0, const float* __restrict__ t1,
                        const float* __restrict__ t2, const float* __restrict__ t3,
                        const float* __restrict__ t4, const float* __restrict__ t5,
                        const float* __restrict__ Wr0, const float* __restrict__ Wr1,
                        const float* __restrict__ Wr2, const float* __restrict__ Wr3,
                        const float* __restrict__ Wr4, const float* __restrict__ Wr5,
                        const float* __restrict__ Wl1, const float* __restrict__ Wl2,
                        const float* __restrict__ c1w, const float* __restrict__ c1b,
                        const float* __restrict__ c2w, const float* __restrict__ c2b) {
    int id = blockIdx.x * blockDim.x + threadIdx.x;
    if (id < BATCH * NNODE * OUT_F) {
        int o = id % 3, node = (id / 3) & 31, b = id / (NNODE * 3);
        float s = 0.f;
        const float* tp;
        tp = t0 + b * 96;                          // size 1, feats 96, idx 0
        for (int i = 0; i < 96;  i++) s += tp[i] * Wr0[i * 3 + o];
        tp = t1 + (b * 2  + (node >> 4)) * 256;    // size 2, rep 16
        for (int i = 0; i < 256; i++) s += tp[i] * Wr1[i * 3 + o];
        tp = t2 + (b * 4  + (node >> 3)) * 256;    // size 4, rep 8
        for (int i = 0; i < 256; i++) s += tp[i] * Wr2[i * 3 + o];
        tp = t3 + (b * 8  + (node >> 2)) * 256;    // size 8, rep 4
        for (int i = 0; i < 256; i++) s += tp[i] * Wr3[i * 3 + o];
        tp = t4 + (b * 16 + (node >> 1)) * 128;    // size 16, rep 2
        for (int i = 0; i < 128; i++) s += tp[i] * Wr4[i * 3 + o];
        tp = t5 + (b * 32 +  node) * 128;          // size 32, rep 1
        for (int i = 0; i < 128; i++) s += tp[i] * Wr5[i * 3 + o];
        g_root[id] = s;
    } else if (id < 1536 + IN_F * OUT_F) {
        int q = id - 1536; int f = q / 3, o = q % 3;
        float s = 0.f;
        for (int t = 0; t < 1280; t++) s += Wl1[f * 1280 + t] * Wl2[t * 3 + o];
        g_Wl[q] = s;
    } else if (id < 1920 + 18) {
        int q = id - 1920; int p = q / 6, c = q % 6;
        float s = 0.f;
        for (int o = 0; o < 64; o++) s += c2w[p * 64 + o] * c1w[o * 6 + c];
        g_ceff[q] = s;
    } else if (id < 1938 + 3) {
        int p = id - 1938;
        float s = c2b[p];
        for (int o = 0; o < 64; o++) s += c2w[p * 64 + o] * c1b[o];
        g_beff[p] = s;
    }
}

// ============================================================
// K1: x[b, n*64+d, :] = root[b,n,:] + leaky(t5[b,n,:] @ W_branch[n]) @ Wl
// Block = (node n, 512-column tile). 128 threads, 4 consecutive cols/thread
// (one LDG.128 per i), 16 batches as 8 packed f32x2 accumulators per column.
// Epilogue fuses leaky + the 128->3 projection; only float4 x hits GMEM.
// ============================================================
__global__ __launch_bounds__(128) void k1_branch(const float* __restrict__ t5,
                                                 const float* __restrict__ Wb) {
    const int n   = blockIdx.x >> 4;     // 32 nodes
    const int jt  = blockIdx.x & 15;     // 16 tiles of 512 cols
    const int j0  = jt * 512;
    const int tid = threadIdx.x;

    __shared__ unsigned long long sa[IN_F * 8];  // [i][bpair] packed (b even|odd)
    __shared__ float sC[16][513];                // leaky'd C, padded vs bank conflicts
    __shared__ float sWl[IN_F * OUT_F];

    {
        int i = tid;  // 128 threads == IN_F
        #pragma unroll
        for (int p = 0; p < 8; p++) {
            float a0 = t5[((2 * p)     * NNODE + n) * IN_F + i];
            float a1 = t5[((2 * p + 1) * NNODE + n) * IN_F + i];
            sa[i * 8 + p] = ((unsigned long long)__float_as_uint(a1) << 32)
                          | (unsigned long long)__float_as_uint(a0);
        }
        for (int q = tid; q < IN_F * OUT_F; q += 128) sWl[q] = g_Wl[q];
    }
    __syncthreads();

    unsigned long long acc[4][8];
    #pragma unroll
    for (int c = 0; c < 4; c++)
        #pragma unroll
        for (int p = 0; p < 8; p++) acc[c][p] = 0ull;

    const float4* wptr =
        (const float4*)(Wb + (size_t)n * IN_F * JCOLS + j0 + 4 * tid);

    #pragma unroll 4
    for (int i = 0; i < IN_F; i++) {
        float4 w = wptr[(size_t)i * (JCOLS / 4)];
        unsigned long long w0 = splat2(w.x), w1 = splat2(w.y),
                           w2 = splat2(w.z), w3 = splat2(w.w);
        #pragma unroll
        for (int p = 0; p < 8; p++) {
            unsigned long long a = sa[i * 8 + p];
            ffma2(acc[0][p], a, w0);
            ffma2(acc[1][p], a, w1);
            ffma2(acc[2][p], a, w2);
            ffma2(acc[3][p], a, w3);
        }
    }

    // leaky -> sC
    #pragma unroll
    for (int c = 0; c < 4; c++) {
        int j = 4 * tid + c;
        #pragma unroll
        for (int p = 0; p < 8; p++) {
            float lo = __uint_as_float((unsigned)(acc[c][p] & 0xffffffffu));
            float hi = __uint_as_float((unsigned)(acc[c][p] >> 32));
            lo = lo >= 0.f ? lo : 0.2f * lo;
            hi = hi >= 0.f ? hi : 0.2f * hi;
            sC[2 * p][j]     = lo;
            sC[2 * p + 1][j] = hi;
        }
    }
    __syncthreads();

    // projection: 4 d-blocks x 16 batches; thread t<64 handles one (d,b)
    if (tid < 64) {
        int d = tid >> 4, b = tid & 15;
        float s0 = 0.f, s1 = 0.f, s2 = 0.f;
        const float* row = &sC[b][d * 128];
        #pragma unroll 4
        for (int f = 0; f < 128; f++) {
            float cv = row[f];
            s0 += cv * sWl[f * 3 + 0];
            s1 += cv * sWl[f * 3 + 1];
            s2 += cv * sWl[f * 3 + 2];
        }
        const float* rp = &g_root[(b * NNODE + n) * 3];
        float x0 = s0 + rp[0], x1 = s1 + rp[1], x2 = s2 + rp[2];
        float xx = x0 * x0 + x1 * x1 + x2 * x2;
        int dglob = jt * 4 + d;
        g_x[b * NPTS + n * DEG + dglob] = make_float4(x0, x1, x2, xx);
    }
}

// ============================================================
// K2: per (b,n): exact top-8 of pd = 2*dot - xxn - xxm over 2048 points
// (register sorted-insert, tie-stable like lax.top_k), then collapsed
// edge-MLP (18 FMA/edge) + max-over-k + bias + leaky.
// ============================================================
__global__ __launch_bounds__(128) void k2_knn(const float* __restrict__ bias,
                                              float* __restrict__ out) {
    const int b    = blockIdx.x >> 4;
    const int tile = blockIdx.x & 15;
    const int tid  = threadIdx.x;

    __shared__ float4 sx[NPTS];     // 32KB
    __shared__ float  sce[18], sbe[3];
    for (int q = tid; q < NPTS; q += 128) sx[q] = g_x[b * NPTS + q];
    if (tid < 18) sce[tid] = g_ceff[tid];
    if (tid < 3)  sbe[tid] = g_beff[tid];
    __syncthreads();

    const int n = tile * 128 + tid;
    const float4 xn = sx[n];

    float val[KNN]; int idx[KNN];
    #pragma unroll
    for (int k = 0; k < KNN; k++) { val[k] = -3.4e38f; idx[k] = 0; }

    for (int m = 0; m < NPTS; m++) {
        float4 xm = sx[m];
        float dot = xn.x * xm.x + xn.y * xm.y + xn.z * xm.z;
        float pd  = 2.f * dot - xn.w - xm.w;
        if (pd > val[KNN - 1]) {           // strict >: earlier index wins ties
            val[KNN - 1] = pd; idx[KNN - 1] = m;
            #pragma unroll
            for (int s = KNN - 1; s >= 1; s--) {
                if (val[s] > val[s - 1]) { // strict >: stable bubble
                    float tv = val[s]; val[s] = val[s - 1]; val[s - 1] = tv;
                    int   ti = idx[s]; idx[s] = idx[s - 1]; idx[s - 1] = ti;
                }
            }
        }
    }

    float h0 = -3.4e38f, h1 = -3.4e38f, h2 = -3.4e38f;
    #pragma unroll
    for (int k = 0; k < KNN; k++) {
        float4 xm = sx[idx[k]];
        float g0 = xm.x - xn.x, g1 = xm.y - xn.y, g2 = xm.z - xn.z;
        float t0 = sbe[0] + sce[0]  * g0 + sce[1]  * g1 + sce[2]  * g2
                          + sce[3]  * xn.x + sce[4]  * xn.y + sce[5]  * xn.z;
        float t1 = sbe[1] + sce[6]  * g0 + sce[7]  * g1 + sce[8]  * g2
                          + sce[9]  * xn.x + sce[10] * xn.y + sce[11] * xn.z;
        float t2 = sbe[2] + sce[12] * g0 + sce[13] * g1 + sce[14] * g2
                          + sce[15] * xn.x + sce[16] * xn.y + sce[17] * xn.z;
        h0 = fmaxf(h0, t0); h1 = fmaxf(h1, t1); h2 = fmaxf(h2, t2);
    }

    const int bi = (n & 63) * 3;           // bias tiled with period DEG=64
    float o0 = h0 + bias[bi + 0];
    float o1 = h1 + bias[bi + 1];
    float o2 = h2 + bias[bi + 2];
    o0 = o0 >= 0.f ? o0 : 0.2f * o0;
    o1 = o1 >= 0.f ? o1 : 0.2f * o1;
    o2 = o2 >= 0.f ? o2 : 0.2f * o2;

    float* op = out + (size_t)(b * NPTS + n) * 3;
    op[0] = o0; op[1] = o1; op[2] = o2;
}

// ============================================================
extern "C" void kernel_launch(void* const* d_in, const int* in_sizes, int n_in,
                              void* d_out, int out_size) {
    const float* t0  = (const float*)d_in[0];
    const float* t1  = (const float*)d_in[1];
    const float* t2  = (const float*)d_in[2];
    const float* t3  = (const float*)d_in[3];
    const float* t4  = (const float*)d_in[4];
    const float* t5  = (const float*)d_in[5];
    const float* Wr0 = (const float*)d_in[6];
    const float* Wr1 = (const float*)d_in[7];
    const float* Wr2 = (const float*)d_in[8];
    const float* Wr3 = (const float*)d_in[9];
    const float* Wr4 = (const float*)d_in[10];
    const float* Wr5 = (const float*)d_in[11];
    const float* Wb  = (const float*)d_in[12];
    const float* Wl1 = (const float*)d_in[13];
    const float* Wl2 = (const float*)d_in[14];
    const float* bia = (const float*)d_in[15];
    const float* c1w = (const float*)d_in[16];
    const float* c1b = (const float*)d_in[17];
    const float* c2w = (const float*)d_in[18];
    const float* c2b = (const float*)d_in[19];

    k0_prep<<<8, 256>>>(t0, t1, t2, t3, t4, t5,
                        Wr0, Wr1, Wr2, Wr3, Wr4, Wr5,
                        Wl1, Wl2, c1w, c1b, c2w, c2b);
    k1_branch<<<NNODE * 16, 128>>>(t5, Wb);
    k2_knn<<<BATCH * 16, 128>>>(bia, (float*)d_out);
}

// round 2
// speedup vs baseline: 1.4742x; 1.4742x over previous
#include <cuda_runtime.h>

#define BATCH 16
#define NNODE 32
#define DEG 64
#define KNN 8
#define IN_F 128
#define OUT_F 3
#define NPTS 2048   // NNODE*DEG
#define JCOLS 8192  // DEG*IN_F

// ---------- device scratch (no allocations allowed) ----------
__device__ float  g_root[BATCH * NNODE * OUT_F];
__device__ float  g_Wl[IN_F * OUT_F];     // collapsed Wl1@Wl2, layout [f*3+o]
__device__ float  g_ceff[OUT_F * 6];      // collapsed c2w@c1w, layout [p*6+c]
__device__ float  g_beff[OUT_F];          // c2w@c1b + c2b
__device__ float4 g_x[BATCH * NPTS];      // (x0,x1,x2, 0.5*||x||^2)

// ---------- packed f32x2 helpers ----------
__device__ __forceinline__ unsigned long long splat2(float w) {
    unsigned long long r;
    asm("mov.b64 %0, {%1, %1};" : "=l"(r) : "f"(w));
    return r;
}
__device__ __forceinline__ void ffma2(unsigned long long& d,
                                      unsigned long long a,
                                      unsigned long long b) {
    asm("fma.rn.f32x2 %0, %1, %2, %0;" : "+l"(d) : "l"(a), "l"(b));
}

// ============================================================
// K0: parallel prep. 641 blocks x 128 threads.
//  blocks [0,512):   root[b][n][0..2]   (b = bid>>5, n = bid&31)
//  blocks [512,640): g_Wl row f = bid-512
//  block  640:       ceff / beff
// ============================================================
__global__ __launch_bounds__(128) void k0_prep(
        const float* __restrict__ t0, const float* __restrict__ t1,
        const float* __restrict__ t2, const float* __restrict__ t3,
        const float* __restrict__ t4, const float* __restrict__ t5,
        const float* __restrict__ Wr0, const float* __restrict__ Wr1,
        const float* __restrict__ Wr2, const float* __restrict__ Wr3,
        const float* __restrict__ Wr4, const float* __restrict__ Wr5,
        const float* __restrict__ Wl1, const float* __restrict__ Wl2,
        const float* __restrict__ c1w, const float* __restrict__ c1b,
        const float* __restrict__ c2w, const float* __restrict__ c2b) {
    const int bid = blockIdx.x;
    const int tid = threadIdx.x;
    __shared__ float red[3][128];

    if (bid < 512) {
        const int b = bid >> 5, n = bid & 31;
        float s0 = 0.f, s1 = 0.f, s2 = 0.f;
        // concatenated feature space: 96 | 256 | 256 | 256 | 128 | 128 = 1120
        for (int idx = tid; idx < 1120; idx += 128) {
            float v; const float* w;
            if (idx < 96) {
                v = t0[b * 96 + idx];                            w = Wr0 + idx * 3;
            } else if (idx < 352) {
                int i = idx - 96;
                v = t1[(b * 2  + (n >> 4)) * 256 + i];           w = Wr1 + i * 3;
            } else if (idx < 608) {
                int i = idx - 352;
                v = t2[(b * 4  + (n >> 3)) * 256 + i];           w = Wr2 + i * 3;
            } else if (idx < 864) {
                int i = idx - 608;
                v = t3[(b * 8  + (n >> 2)) * 256 + i];           w = Wr3 + i * 3;
            } else if (idx < 992) {
                int i = idx - 864;
                v = t4[(b * 16 + (n >> 1)) * 128 + i];           w = Wr4 + i * 3;
            } else {
                int i = idx - 992;
                v = t5[(b * 32 +  n      ) * 128 + i];           w = Wr5 + i * 3;
            }
            s0 = fmaf(v, w[0], s0); s1 = fmaf(v, w[1], s1); s2 = fmaf(v, w[2], s2);
        }
        red[0][tid] = s0; red[1][tid] = s1; red[2][tid] = s2;
        __syncthreads();
        for (int off = 64; off > 0; off >>= 1) {
            if (tid < off) {
                red[0][tid] += red[0][tid + off];
                red[1][tid] += red[1][tid + off];
                red[2][tid] += red[2][tid + off];
            }
            __syncthreads();
        }
        if (tid < 3) g_root[(b * NNODE + n) * 3 + tid] = red[tid][0];
    } else if (bid < 640) {
        const int f = bid - 512;
        float s0 = 0.f, s1 = 0.f, s2 = 0.f;
        for (int tt = tid; tt < 1280; tt += 128) {
            float v = Wl1[f * 1280 + tt];
            s0 = fmaf(v, Wl2[tt * 3 + 0], s0);
            s1 = fmaf(v, Wl2[tt * 3 + 1], s1);
            s2 = fmaf(v, Wl2[tt * 3 + 2], s2);
        }
        red[0][tid] = s0; red[1][tid] = s1; red[2][tid] = s2;
        __syncthreads();
        for (int off = 64; off > 0; off >>= 1) {
            if (tid < off) {
                red[0][tid] += red[0][tid + off];
                red[1][tid] += red[1][tid + off];
                red[2][tid] += red[2][tid + off];
            }
            __syncthreads();
        }
        if (tid < 3) g_Wl[f * 3 + tid] = red[tid][0];
    } else {
        // ceff: 18 outputs, beff: 3 outputs (tiny; 64-length dots)
        if (tid < 18) {
            int p = tid / 6, c = tid % 6;
            float s = 0.f;
            for (int o = 0; o < 64; o++) s = fmaf(c2w[p * 64 + o], c1w[o * 6 + c], s);
            g_ceff[tid] = s;
        } else if (tid < 21) {
            int p = tid - 18;
            float s = c2b[p];
            for (int o = 0; o < 64; o++) s = fmaf(c2w[p * 64 + o], c1b[o], s);
            g_beff[p] = s;
        }
    }
}

// ============================================================
// K1: x[b, n*64+d, :] = root[b,n,:] + leaky(t5[b,n,:] @ W_branch[n]) @ Wl
// Block = (node n, 512-col tile). 128 threads, 4 cols/thread (LDG.128/row),
// 16 batches as 8 packed f32x2 accumulators per column. Epilogue fuses
// leaky + the 128->3 projection; stores (x, 0.5*||x||^2) only.
// ============================================================
__global__ __launch_bounds__(128) void k1_branch(const float* __restrict__ t5,
                                                 const float* __restrict__ Wb) {
    const int n   = blockIdx.x >> 4;     // 32 nodes
    const int jt  = blockIdx.x & 15;     // 16 tiles of 512 cols
    const int j0  = jt * 512;
    const int tid = threadIdx.x;

    __shared__ __align__(16) unsigned long long sa[IN_F * 8];  // [i][bpair]
    __shared__ float sC[16][513];
    __shared__ float sWl[IN_F * OUT_F];

    {
        int i = tid;  // 128 threads == IN_F
        #pragma unroll
        for (int p = 0; p < 8; p++) {
            float a0 = t5[((2 * p)     * NNODE + n) * IN_F + i];
            float a1 = t5[((2 * p + 1) * NNODE + n) * IN_F + i];
            sa[i * 8 + p] = ((unsigned long long)__float_as_uint(a1) << 32)
                          | (unsigned long long)__float_as_uint(a0);
        }
        for (int q = tid; q < IN_F * OUT_F; q += 128) sWl[q] = g_Wl[q];
    }
    __syncthreads();

    unsigned long long acc[4][8];
    #pragma unroll
    for (int c = 0; c < 4; c++)
        #pragma unroll
        for (int p = 0; p < 8; p++) acc[c][p] = 0ull;

    const float4* wptr =
        (const float4*)(Wb + (size_t)n * IN_F * JCOLS + j0 + 4 * tid);

    #pragma unroll 4
    for (int i = 0; i < IN_F; i++) {
        float4 w = wptr[(size_t)i * (JCOLS / 4)];
        unsigned long long w0 = splat2(w.x), w1 = splat2(w.y),
                           w2 = splat2(w.z), w3 = splat2(w.w);
        const ulonglong2* sap = (const ulonglong2*)(sa + i * 8);
        #pragma unroll
        for (int q = 0; q < 4; q++) {
            ulonglong2 ap = sap[q];
            ffma2(acc[0][2 * q], ap.x, w0);
            ffma2(acc[1][2 * q], ap.x, w1);
            ffma2(acc[2][2 * q], ap.x, w2);
            ffma2(acc[3][2 * q], ap.x, w3);
            ffma2(acc[0][2 * q + 1], ap.y, w0);
            ffma2(acc[1][2 * q + 1], ap.y, w1);
            ffma2(acc[2][2 * q + 1], ap.y, w2);
            ffma2(acc[3][2 * q + 1], ap.y, w3);
        }
    }

    // leaky -> sC
    #pragma unroll
    for (int c = 0; c < 4; c++) {
        int j = 4 * tid + c;
        #pragma unroll
        for (int p = 0; p < 8; p++) {
            float lo = __uint_as_float((unsigned)(acc[c][p] & 0xffffffffu));
            float hi = __uint_as_float((unsigned)(acc[c][p] >> 32));
            lo = lo >= 0.f ? lo : 0.2f * lo;
            hi = hi >= 0.f ? hi : 0.2f * hi;
            sC[2 * p][j]     = lo;
            sC[2 * p + 1][j] = hi;
        }
    }
    __syncthreads();

    // projection: 4 d-blocks x 16 batches; thread t<64 handles one (d,b)
    if (tid < 64) {
        int d = tid >> 4, b = tid & 15;
        float s0 = 0.f, s1 = 0.f, s2 = 0.f;
        const float* row = &sC[b][d * 128];
        #pragma unroll 4
        for (int f = 0; f < 128; f++) {
            float cv = row[f];
            s0 = fmaf(cv, sWl[f * 3 + 0], s0);
            s1 = fmaf(cv, sWl[f * 3 + 1], s1);
            s2 = fmaf(cv, sWl[f * 3 + 2], s2);
        }
        const float* rp = &g_root[(b * NNODE + n) * 3];
        float x0 = s0 + rp[0], x1 = s1 + rp[1], x2 = s2 + rp[2];
        float hxx = 0.5f * (x0 * x0 + x1 * x1 + x2 * x2);
        int dglob = jt * 4 + d;
        g_x[b * NPTS + n * DEG + dglob] = make_float4(x0, x1, x2, hxx);
    }
}

// ============================================================
// K2: per (b,n): exact top-8 of score = dot(xn,xm) - 0.5*xxn - 0.5*xxm
// (monotone transform of pd; ordering identical). Group-of-4 candidates
// with max-prefilter branch; early-exit tail-up bubble (tie-stable).
// Then collapsed edge-MLP + max-over-k + bias + leaky.
// ============================================================
__device__ __forceinline__ void topk_insert(float v, int m, float* val, int* idx) {
    val[KNN - 1] = v; idx[KNN - 1] = m;
    #pragma unroll
    for (int s = KNN - 1; s >= 1; s--) {
        if (val[s] > val[s - 1]) {      // strict: earlier index wins ties
            float tv = val[s]; val[s] = val[s - 1]; val[s - 1] = tv;
            int   ti = idx[s]; idx[s] = idx[s - 1]; idx[s - 1] = ti;
        } else break;
    }
}

__global__ __launch_bounds__(128) void k2_knn(const float* __restrict__ bias,
                                              float* __restrict__ out) {
    const int b    = blockIdx.x >> 4;
    const int tile = blockIdx.x & 15;
    const int tid  = threadIdx.x;

    __shared__ float4 sx[NPTS];     // 32KB
    __shared__ float  sce[18], sbe[3];
    for (int q = tid; q < NPTS; q += 128) sx[q] = g_x[b * NPTS + q];
    if (tid < 18) sce[tid] = g_ceff[tid];
    if (tid < 3)  sbe[tid] = g_beff[tid];
    __syncthreads();

    const int n = tile * 128 + tid;
    const float4 xn = sx[n];
    const float nx = xn.x, ny = xn.y, nz = xn.z, negw = -xn.w;

    float val[KNN]; int idx[KNN];
    #pragma unroll
    for (int k = 0; k < KNN; k++) { val[k] = -3.4e38f; idx[k] = 0; }

    #pragma unroll 1
    for (int m0 = 0; m0 < NPTS; m0 += 4) {
        float4 xa = sx[m0], xb = sx[m0 + 1], xc = sx[m0 + 2], xd = sx[m0 + 3];
        float p0 = fmaf(nx, xa.x, fmaf(ny, xa.y, fmaf(nz, xa.z, negw - xa.w)));
        float p1 = fmaf(nx, xb.x, fmaf(ny, xb.y, fmaf(nz, xb.z, negw - xb.w)));
        float p2 = fmaf(nx, xc.x, fmaf(ny, xc.y, fmaf(nz, xc.z, negw - xc.w)));
        float p3 = fmaf(nx, xd.x, fmaf(ny, xd.y, fmaf(nz, xd.z, negw - xd.w)));
        float gm = fmaxf(fmaxf(p0, p1), fmaxf(p2, p3));
        if (gm > val[KNN - 1]) {
            if (p0 > val[KNN - 1]) topk_insert(p0, m0,     val, idx);
            if (p1 > val[KNN - 1]) topk_insert(p1, m0 + 1, val, idx);
            if (p2 > val[KNN - 1]) topk_insert(p2, m0 + 2, val, idx);
            if (p3 > val[KNN - 1]) topk_insert(p3, m0 + 3, val, idx);
        }
    }

    float h0 = -3.4e38f, h1 = -3.4e38f, h2 = -3.4e38f;
    #pragma unroll
    for (int k = 0; k < KNN; k++) {
        float4 xm = sx[idx[k]];
        float g0 = xm.x - nx, g1 = xm.y - ny, g2 = xm.z - nz;
        float t0 = sbe[0] + sce[0]  * g0 + sce[1]  * g1 + sce[2]  * g2
                          + sce[3]  * nx + sce[4]  * ny + sce[5]  * nz;
        float t1 = sbe[1] + sce[6]  * g0 + sce[7]  * g1 + sce[8]  * g2
                          + sce[9]  * nx + sce[10] * ny + sce[11] * nz;
        float t2 = sbe[2] + sce[12] * g0 + sce[13] * g1 + sce[14] * g2
                          + sce[15] * nx + sce[16] * ny + sce[17] * nz;
        h0 = fmaxf(h0, t0); h1 = fmaxf(h1, t1); h2 = fmaxf(h2, t2);
    }

    const int bi = (n & 63) * 3;           // bias tiled with period DEG=64
    float o0 = h0 + bias[bi + 0];
    float o1 = h1 + bias[bi + 1];
    float o2 = h2 + bias[bi + 2];
    o0 = o0 >= 0.f ? o0 : 0.2f * o0;
    o1 = o1 >= 0.f ? o1 : 0.2f * o1;
    o2 = o2 >= 0.f ? o2 : 0.2f * o2;

    float* op = out + (size_t)(b * NPTS + n) * 3;
    op[0] = o0; op[1] = o1; op[2] = o2;
}

// ============================================================
extern "C" void kernel_launch(void* const* d_in, const int* in_sizes, int n_in,
                              void* d_out, int out_size) {
    const float* t0  = (const float*)d_in[0];
    const float* t1  = (const float*)d_in[1];
    const float* t2  = (const float*)d_in[2];
    const float* t3  = (const float*)d_in[3];
    const float* t4  = (const float*)d_in[4];
    const float* t5  = (const float*)d_in[5];
    const float* Wr0 = (const float*)d_in[6];
    const float* Wr1 = (const float*)d_in[7];
    const float* Wr2 = (const float*)d_in[8];
    const float* Wr3 = (const float*)d_in[9];
    const float* Wr4 = (const float*)d_in[10];
    const float* Wr5 = (const float*)d_in[11];
    const float* Wb  = (const float*)d_in[12];
    const float* Wl1 = (const float*)d_in[13];
    const float* Wl2 = (const float*)d_in[14];
    const float* bia = (const float*)d_in[15];
    const float* c1w = (const float*)d_in[16];
    const float* c1b = (const float*)d_in[17];
    const float* c2w = (const float*)d_in[18];
    const float* c2b = (const float*)d_in[19];

    k0_prep<<<641, 128>>>(t0, t1, t2, t3, t4, t5,
                          Wr0, Wr1, Wr2, Wr3, Wr4, Wr5,
                          Wl1, Wl2, c1w, c1b, c2w, c2b);
    k1_branch<<<NNODE * 16, 128>>>(t5, Wb);
    k2_knn<<<BATCH * 16, 128>>>(bia, (float*)d_out);
}